// round 1
// baseline (speedup 1.0000x reference)
#include <cuda_runtime.h>
#include <math.h>

#define NB     4
#define S_LEN  2048
#define DM     1024
#define NH     16
#define DK     64

// Scratch: projections and attention output. __device__ globals (no allocs).
__device__ float g_Q[NB * S_LEN * DM];
__device__ float g_K[NB * S_LEN * DM];
__device__ float g_V[NB * S_LEN * DM];
__device__ float g_A[NB * S_LEN * DM];

// ---------------------------------------------------------------------------
// SGEMM (NT): C[M,N] = A[M,K] @ B[N,K]^T + bias[N]
// Tile 128x128x8, 256 threads, 8x8 register blocking.
// M=8192, N=1024, K=1024 (all divide tile dims evenly; no bounds checks).
// ---------------------------------------------------------------------------
#define BM 128
#define BN 128
#define BKT 8

__global__ __launch_bounds__(256, 2)
void gemm_nt_bias(const float* __restrict__ A, const float* __restrict__ B,
                  const float* __restrict__ bias, float* __restrict__ C,
                  int M, int N, int K)
{
    __shared__ float As[BKT][BM];
    __shared__ float Bs[BKT][BN];

    const int tid = threadIdx.x;
    const int bm  = blockIdx.y * BM;
    const int bn  = blockIdx.x * BN;
    const int tx  = tid & 15;   // 0..15 -> 8 cols each
    const int ty  = tid >> 4;   // 0..15 -> 8 rows each

    // load mapping: each thread loads one float4 of A and one of B per k-tile
    const int lr = tid >> 1;          // 0..127 row in tile
    const int lk = (tid & 1) * 4;     // 0 or 4

    const float* Ap = A + (size_t)(bm + lr) * K + lk;
    const float* Bp = B + (size_t)(bn + lr) * K + lk;

    float acc[8][8];
#pragma unroll
    for (int i = 0; i < 8; i++)
#pragma unroll
        for (int j = 0; j < 8; j++) acc[i][j] = 0.f;

    for (int k0 = 0; k0 < K; k0 += BKT) {
        float4 av = *(const float4*)(Ap + k0);
        float4 bv = *(const float4*)(Bp + k0);
        As[lk + 0][lr] = av.x; As[lk + 1][lr] = av.y;
        As[lk + 2][lr] = av.z; As[lk + 3][lr] = av.w;
        Bs[lk + 0][lr] = bv.x; Bs[lk + 1][lr] = bv.y;
        Bs[lk + 2][lr] = bv.z; Bs[lk + 3][lr] = bv.w;
        __syncthreads();

#pragma unroll
        for (int kk = 0; kk < BKT; kk++) {
            float4 a0 = *(const float4*)&As[kk][ty * 8];
            float4 a1 = *(const float4*)&As[kk][ty * 8 + 4];
            float4 b0 = *(const float4*)&Bs[kk][tx * 8];
            float4 b1 = *(const float4*)&Bs[kk][tx * 8 + 4];
            float a[8] = {a0.x, a0.y, a0.z, a0.w, a1.x, a1.y, a1.z, a1.w};
            float b[8] = {b0.x, b0.y, b0.z, b0.w, b1.x, b1.y, b1.z, b1.w};
#pragma unroll
            for (int i = 0; i < 8; i++)
#pragma unroll
                for (int j = 0; j < 8; j++)
                    acc[i][j] += a[i] * b[j];
        }
        __syncthreads();
    }

#pragma unroll
    for (int i = 0; i < 8; i++) {
        float* cp = C + (size_t)(bm + ty * 8 + i) * N + bn + tx * 8;
#pragma unroll
        for (int j = 0; j < 8; j++)
            cp[j] = acc[i][j] + bias[bn + tx * 8 + j];
    }
}

// ---------------------------------------------------------------------------
// Flash attention: 1 thread = 1 query row. BQ=128 rows/block, BK=32 keys/tile.
// Q row (pre-scaled) + O accumulator in registers; K/V/score tiles in smem.
// grid = (S/BQ, NH, NB), 128 threads.
// ---------------------------------------------------------------------------
#define BQ  128
#define BKA 32

__global__ __launch_bounds__(BQ)
void flash_attn(const float* __restrict__ Q, const float* __restrict__ K,
                const float* __restrict__ V, const int* __restrict__ mask,
                float* __restrict__ O)
{
    __shared__ float Ks[BKA][DK];
    __shared__ float Vs[BKA][DK];
    __shared__ float Ssc[BQ][BKA + 1];

    const int tid = threadIdx.x;
    const int b   = blockIdx.z;
    const int h   = blockIdx.y;
    const int qi  = blockIdx.x * BQ + tid;

    const float scale = 0.125f;  // 1/sqrt(64)

    // Q row into registers, pre-scaled
    float qreg[DK];
    {
        const float* qp = Q + ((size_t)b * S_LEN + qi) * DM + h * DK;
#pragma unroll
        for (int d = 0; d < DK; d += 4) {
            float4 v4 = *(const float4*)(qp + d);
            qreg[d + 0] = v4.x * scale; qreg[d + 1] = v4.y * scale;
            qreg[d + 2] = v4.z * scale; qreg[d + 3] = v4.w * scale;
        }
    }

    float m = -INFINITY, l = 0.f;
    float o[DK];
#pragma unroll
    for (int d = 0; d < DK; d++) o[d] = 0.f;

    const int* mrow = mask + ((size_t)b * S_LEN + qi) * S_LEN;

    // tile-load mapping: 32 rows x 64 cols, 128 threads, 16 floats each
    const int r = tid >> 2;
    const int c = (tid & 3) * 16;

    for (int kt = 0; kt < S_LEN; kt += BKA) {
        const float* kp = K + ((size_t)b * S_LEN + kt + r) * DM + h * DK + c;
        const float* vp = V + ((size_t)b * S_LEN + kt + r) * DM + h * DK + c;
#pragma unroll
        for (int i = 0; i < 16; i += 4) {
            *(float4*)&Ks[r][c + i] = *(const float4*)(kp + i);
            *(float4*)&Vs[r][c + i] = *(const float4*)(vp + i);
        }
        __syncthreads();

        // scores for this thread's q row
        float tmax = -INFINITY;
#pragma unroll 4
        for (int j = 0; j < BKA; j++) {
            float s = 0.f;
#pragma unroll
            for (int d = 0; d < DK; d++)
                s += qreg[d] * Ks[j][d];
            if (mrow[kt + j] == 0) s = -INFINITY;
            Ssc[tid][j] = s;
            tmax = fmaxf(tmax, s);
        }

        float mnew = fmaxf(m, tmax);
        float corr = (m == -INFINITY) ? 0.f : __expf(m - mnew);
        l *= corr;
#pragma unroll
        for (int d = 0; d < DK; d++) o[d] *= corr;

#pragma unroll 2
        for (int j = 0; j < BKA; j++) {
            float p = __expf(Ssc[tid][j] - mnew);
            l += p;
#pragma unroll
            for (int d = 0; d < DK; d++)
                o[d] += p * Vs[j][d];
        }
        m = mnew;
        __syncthreads();
    }

    const float inv = 1.f / l;
    float* op = O + ((size_t)b * S_LEN + qi) * DM + h * DK;
#pragma unroll
    for (int d = 0; d < DK; d += 4) {
        float4 v4 = make_float4(o[d] * inv, o[d + 1] * inv,
                                o[d + 2] * inv, o[d + 3] * inv);
        *(float4*)(op + d) = v4;
    }
}

// ---------------------------------------------------------------------------
// launch
// ---------------------------------------------------------------------------
extern "C" void kernel_launch(void* const* d_in, const int* in_sizes, int n_in,
                              void* d_out, int out_size)
{
    const float* q    = (const float*)d_in[0];
    const float* k    = (const float*)d_in[1];
    const float* v    = (const float*)d_in[2];
    const int*   mask = (const int*)  d_in[3];
    const float* W_q  = (const float*)d_in[4];
    const float* b_q  = (const float*)d_in[5];
    const float* W_k  = (const float*)d_in[6];
    const float* b_k  = (const float*)d_in[7];
    const float* W_v  = (const float*)d_in[8];
    const float* b_v  = (const float*)d_in[9];
    const float* W_o  = (const float*)d_in[10];
    const float* b_o  = (const float*)d_in[11];
    float* out = (float*)d_out;

    float *Qb, *Kb, *Vb, *Ab;
    cudaGetSymbolAddress((void**)&Qb, g_Q);
    cudaGetSymbolAddress((void**)&Kb, g_K);
    cudaGetSymbolAddress((void**)&Vb, g_V);
    cudaGetSymbolAddress((void**)&Ab, g_A);

    const int M = NB * S_LEN;   // 8192
    dim3 ggrid(DM / BN, M / BM);  // (8, 64)

    gemm_nt_bias<<<ggrid, 256>>>(q, W_q, b_q, Qb, M, DM, DM);
    gemm_nt_bias<<<ggrid, 256>>>(k, W_k, b_k, Kb, M, DM, DM);
    gemm_nt_bias<<<ggrid, 256>>>(v, W_v, b_v, Vb, M, DM, DM);

    dim3 agrid(S_LEN / BQ, NH, NB);  // (16, 16, 4)
    flash_attn<<<agrid, BQ>>>(Qb, Kb, Vb, mask, Ab);

    gemm_nt_bias<<<ggrid, 256>>>(Ab, W_o, b_o, out, M, DM, DM);
}

// round 2
// speedup vs baseline: 2.6995x; 2.6995x over previous
#include <cuda_runtime.h>
#include <math.h>

#define NB     4
#define S_LEN  2048
#define DM     1024
#define NH     16
#define DK     64

typedef unsigned int uint32;

// Scratch (no allocations allowed)
__device__ float g_Q[NB * S_LEN * DM];
__device__ float g_K[NB * S_LEN * DM];
__device__ float g_V[NB * S_LEN * DM];
__device__ float g_A[NB * S_LEN * DM];

// ---------------------------------------------------------------------------
// helpers
// ---------------------------------------------------------------------------
__device__ __forceinline__ float tf32f(float x) {
    float r;
    asm("cvt.rna.tf32.f32 %0, %1;" : "=f"(r) : "f"(x));
    return r;
}

__device__ __forceinline__ void mma_tf32(float* c, const uint32* a, const uint32* b) {
    asm volatile(
        "mma.sync.aligned.m16n8k8.row.col.f32.tf32.tf32.f32 "
        "{%0,%1,%2,%3}, {%4,%5,%6,%7}, {%8,%9}, {%0,%1,%2,%3};"
        : "+f"(c[0]), "+f"(c[1]), "+f"(c[2]), "+f"(c[3])
        : "r"(a[0]), "r"(a[1]), "r"(a[2]), "r"(a[3]), "r"(b[0]), "r"(b[1]));
}

// ---------------------------------------------------------------------------
// tf32 MMA GEMM (NT): C[M,N] = A[M,K] @ B[N,K]^T + bias[N]
// 128x128 block tile, BK=16, 8 warps (2x4), warp tile 64x32, m16n8k8.
// smem row stride 20 floats (20 mod 32 == 4*?; pattern (20g+t) mod 32 is a
// full permutation for g in 0..7, t in 0..3 -> conflict-free frag loads).
// ---------------------------------------------------------------------------
#define GBM 128
#define GBN 128
#define GBK 16
#define GST 20

__global__ __launch_bounds__(256, 2)
void gemm_tf32(const float* __restrict__ A, const float* __restrict__ B,
               const float* __restrict__ bias, float* __restrict__ C,
               int M, int N, int K)
{
    __shared__ __align__(16) float As[GBM][GST];
    __shared__ __align__(16) float Bs[GBN][GST];

    const int tid  = threadIdx.x;
    const int wid  = tid >> 5, lane = tid & 31;
    const int g    = lane >> 2, t = lane & 3;
    const int bm   = blockIdx.y * GBM, bn = blockIdx.x * GBN;
    const int warpM = (wid & 1) * 64;
    const int warpN = (wid >> 1) * 32;

    // global-load mapping: 256 threads, 2 float4 each per operand per tile
    const int lr = tid >> 2;           // 0..63
    const int lc = (tid & 3) * 4;      // 0,4,8,12

    const float* Ag = A + (size_t)(bm + lr) * K + lc;
    const float* Bg = B + (size_t)(bn + lr) * K + lc;
    const size_t rowStep = (size_t)64 * K;

    float acc[4][4][4];
#pragma unroll
    for (int mi = 0; mi < 4; mi++)
#pragma unroll
        for (int ni = 0; ni < 4; ni++)
#pragma unroll
            for (int c = 0; c < 4; c++) acc[mi][ni][c] = 0.f;

    float4 pa0 = *(const float4*)(Ag);
    float4 pa1 = *(const float4*)(Ag + rowStep);
    float4 pb0 = *(const float4*)(Bg);
    float4 pb1 = *(const float4*)(Bg + rowStep);

    for (int k0 = 0; k0 < K; k0 += GBK) {
        // store prefetched tile (tf32-rounded)
        float4 w;
        w.x = tf32f(pa0.x); w.y = tf32f(pa0.y); w.z = tf32f(pa0.z); w.w = tf32f(pa0.w);
        *(float4*)&As[lr][lc] = w;
        w.x = tf32f(pa1.x); w.y = tf32f(pa1.y); w.z = tf32f(pa1.z); w.w = tf32f(pa1.w);
        *(float4*)&As[lr + 64][lc] = w;
        w.x = tf32f(pb0.x); w.y = tf32f(pb0.y); w.z = tf32f(pb0.z); w.w = tf32f(pb0.w);
        *(float4*)&Bs[lr][lc] = w;
        w.x = tf32f(pb1.x); w.y = tf32f(pb1.y); w.z = tf32f(pb1.z); w.w = tf32f(pb1.w);
        *(float4*)&Bs[lr + 64][lc] = w;
        __syncthreads();

        if (k0 + GBK < K) {
            pa0 = *(const float4*)(Ag + k0 + GBK);
            pa1 = *(const float4*)(Ag + rowStep + k0 + GBK);
            pb0 = *(const float4*)(Bg + k0 + GBK);
            pb1 = *(const float4*)(Bg + rowStep + k0 + GBK);
        }

#pragma unroll
        for (int kk = 0; kk < GBK; kk += 8) {
            uint32 af[4][4];
#pragma unroll
            for (int mi = 0; mi < 4; mi++) {
                int r0 = warpM + mi * 16 + g;
                af[mi][0] = __float_as_uint(As[r0][kk + t]);
                af[mi][1] = __float_as_uint(As[r0 + 8][kk + t]);
                af[mi][2] = __float_as_uint(As[r0][kk + t + 4]);
                af[mi][3] = __float_as_uint(As[r0 + 8][kk + t + 4]);
            }
            uint32 bf[4][2];
#pragma unroll
            for (int ni = 0; ni < 4; ni++) {
                int c0 = warpN + ni * 8 + g;
                bf[ni][0] = __float_as_uint(Bs[c0][kk + t]);
                bf[ni][1] = __float_as_uint(Bs[c0][kk + t + 4]);
            }
#pragma unroll
            for (int mi = 0; mi < 4; mi++)
#pragma unroll
                for (int ni = 0; ni < 4; ni++)
                    mma_tf32(acc[mi][ni], af[mi], bf[ni]);
        }
        __syncthreads();
    }

    // epilogue: + bias
#pragma unroll
    for (int mi = 0; mi < 4; mi++) {
        int r0 = bm + warpM + mi * 16 + g;
#pragma unroll
        for (int ni = 0; ni < 4; ni++) {
            int c0 = bn + warpN + ni * 8 + 2 * t;
            float2 bs = *(const float2*)(bias + c0);
            float2 v0 = make_float2(acc[mi][ni][0] + bs.x, acc[mi][ni][1] + bs.y);
            *(float2*)(C + (size_t)r0 * N + c0) = v0;
            float2 v1 = make_float2(acc[mi][ni][2] + bs.x, acc[mi][ni][3] + bs.y);
            *(float2*)(C + (size_t)(r0 + 8) * N + c0) = v1;
        }
    }
}

// ---------------------------------------------------------------------------
// flash attention with tf32 MMA (FA2-style):
// block = 64 q rows, 4 warps x 16 rows; KV tile = 64 keys; head dim 64.
// Q fragments register-resident; P frags via quad shuffles; mask as bitmask.
// Ks stride 68 -> frag bank = (4g+t) full permutation; Vs stride 72 -> (8t+g).
// ---------------------------------------------------------------------------
#define FBQ 64
#define FTK 64
#define KST 68
#define VST 72

__global__ __launch_bounds__(128, 3)
void flash_mma(const float* __restrict__ Q, const float* __restrict__ K,
               const float* __restrict__ V, const int* __restrict__ mask,
               float* __restrict__ O)
{
    __shared__ __align__(16) float Ks[FTK][KST];
    __shared__ __align__(16) float Vs[FTK][VST];
    __shared__ uint32 Msk[FBQ][2];

    const int tid  = threadIdx.x;
    const int wid  = tid >> 5, lane = tid & 31;
    const int g    = lane >> 2, t = lane & 3;
    const int b    = blockIdx.z, h = blockIdx.y;
    const int q0   = blockIdx.x * FBQ;
    const int wq   = wid * 16;

    const int sr = tid >> 1;            // staging row 0..63
    const int sc = (tid & 1) * 32;      // staging col half

    // ---- stage Q (scaled 1/sqrt(64), tf32-rounded) into Ks, extract frags ----
    {
        const float* qp = Q + ((size_t)b * S_LEN + q0 + sr) * DM + h * DK + sc;
#pragma unroll
        for (int i = 0; i < 8; i++) {
            float4 v = *(const float4*)(qp + 4 * i);
            float4 w;
            w.x = tf32f(v.x * 0.125f); w.y = tf32f(v.y * 0.125f);
            w.z = tf32f(v.z * 0.125f); w.w = tf32f(v.w * 0.125f);
            *(float4*)&Ks[sr][sc + 4 * i] = w;
        }
    }
    __syncthreads();
    uint32 qf[8][4];
#pragma unroll
    for (int kk = 0; kk < 8; kk++) {
        qf[kk][0] = __float_as_uint(Ks[wq + g][8 * kk + t]);
        qf[kk][1] = __float_as_uint(Ks[wq + g + 8][8 * kk + t]);
        qf[kk][2] = __float_as_uint(Ks[wq + g][8 * kk + t + 4]);
        qf[kk][3] = __float_as_uint(Ks[wq + g + 8][8 * kk + t + 4]);
    }
    __syncthreads();

    float o[8][4];
#pragma unroll
    for (int nd = 0; nd < 8; nd++)
#pragma unroll
        for (int c = 0; c < 4; c++) o[nd][c] = 0.f;

    float m_a = -1e30f, m_b = -1e30f, l_a = 0.f, l_b = 0.f;

    for (int kt = 0; kt < S_LEN; kt += FTK) {
        // ---- stage K, V tiles (tf32) + mask bits ----
        {
            const float* kp = K + ((size_t)b * S_LEN + kt + sr) * DM + h * DK + sc;
            const float* vp = V + ((size_t)b * S_LEN + kt + sr) * DM + h * DK + sc;
#pragma unroll
            for (int i = 0; i < 8; i++) {
                float4 kv = *(const float4*)(kp + 4 * i);
                float4 vv = *(const float4*)(vp + 4 * i);
                float4 kw, vw;
                kw.x = tf32f(kv.x); kw.y = tf32f(kv.y); kw.z = tf32f(kv.z); kw.w = tf32f(kv.w);
                vw.x = tf32f(vv.x); vw.y = tf32f(vv.y); vw.z = tf32f(vv.z); vw.w = tf32f(vv.w);
                *(float4*)&Ks[sr][sc + 4 * i] = kw;
                *(float4*)&Vs[sr][sc + 4 * i] = vw;
            }
            const int* mp = mask + ((size_t)b * S_LEN + q0 + sr) * S_LEN + kt + sc;
            uint32 bits = 0;
#pragma unroll
            for (int i = 0; i < 8; i++) {
                int4 mv = *(const int4*)(mp + 4 * i);
                bits |= (mv.x != 0 ? 1u : 0u) << (4 * i);
                bits |= (mv.y != 0 ? 1u : 0u) << (4 * i + 1);
                bits |= (mv.z != 0 ? 1u : 0u) << (4 * i + 2);
                bits |= (mv.w != 0 ? 1u : 0u) << (4 * i + 3);
            }
            Msk[sr][tid & 1] = bits;
        }
        __syncthreads();

        // ---- S = Q K^T ----
        float sp[8][4];
#pragma unroll
        for (int nk = 0; nk < 8; nk++)
#pragma unroll
            for (int c = 0; c < 4; c++) sp[nk][c] = 0.f;

#pragma unroll
        for (int kk = 0; kk < 8; kk++) {
#pragma unroll
            for (int nk = 0; nk < 8; nk++) {
                uint32 bb[2];
                bb[0] = __float_as_uint(Ks[8 * nk + g][8 * kk + t]);
                bb[1] = __float_as_uint(Ks[8 * nk + g][8 * kk + t + 4]);
                mma_tf32(sp[nk], qf[kk], bb);
            }
        }

        // ---- mask ----
        uint32 wa0 = Msk[wq + g][0], wa1 = Msk[wq + g][1];
        uint32 wb0 = Msk[wq + g + 8][0], wb1 = Msk[wq + g + 8][1];
#pragma unroll
        for (int nk = 0; nk < 8; nk++) {
            int sh = (8 * nk + 2 * t) & 31;
            uint32 wa = (nk < 4) ? wa0 : wa1;
            uint32 wb = (nk < 4) ? wb0 : wb1;
            if (!((wa >> sh) & 1))       sp[nk][0] = -1e30f;
            if (!((wa >> (sh + 1)) & 1)) sp[nk][1] = -1e30f;
            if (!((wb >> sh) & 1))       sp[nk][2] = -1e30f;
            if (!((wb >> (sh + 1)) & 1)) sp[nk][3] = -1e30f;
        }

        // ---- online softmax (rows g and g+8, stats shared across quad) ----
        float mxa = -1e30f, mxb = -1e30f;
#pragma unroll
        for (int nk = 0; nk < 8; nk++) {
            mxa = fmaxf(mxa, fmaxf(sp[nk][0], sp[nk][1]));
            mxb = fmaxf(mxb, fmaxf(sp[nk][2], sp[nk][3]));
        }
        mxa = fmaxf(mxa, __shfl_xor_sync(0xffffffffu, mxa, 1));
        mxa = fmaxf(mxa, __shfl_xor_sync(0xffffffffu, mxa, 2));
        mxb = fmaxf(mxb, __shfl_xor_sync(0xffffffffu, mxb, 1));
        mxb = fmaxf(mxb, __shfl_xor_sync(0xffffffffu, mxb, 2));

        float mna = fmaxf(m_a, mxa), mnb = fmaxf(m_b, mxb);
        float ca = __expf(m_a - mna), cb = __expf(m_b - mnb);

        float sa = 0.f, sb = 0.f;
#pragma unroll
        for (int nk = 0; nk < 8; nk++) {
            sp[nk][0] = __expf(sp[nk][0] - mna); sa += sp[nk][0];
            sp[nk][1] = __expf(sp[nk][1] - mna); sa += sp[nk][1];
            sp[nk][2] = __expf(sp[nk][2] - mnb); sb += sp[nk][2];
            sp[nk][3] = __expf(sp[nk][3] - mnb); sb += sp[nk][3];
        }
        sa += __shfl_xor_sync(0xffffffffu, sa, 1);
        sa += __shfl_xor_sync(0xffffffffu, sa, 2);
        sb += __shfl_xor_sync(0xffffffffu, sb, 1);
        sb += __shfl_xor_sync(0xffffffffu, sb, 2);

        l_a = l_a * ca + sa;  l_b = l_b * cb + sb;
        m_a = mna;            m_b = mnb;

#pragma unroll
        for (int nd = 0; nd < 8; nd++) {
            o[nd][0] *= ca; o[nd][1] *= ca;
            o[nd][2] *= cb; o[nd][3] *= cb;
        }

        // ---- O += P V  (P a-frags via quad shuffles) ----
        const int src0 = 4 * g + (t >> 1);
        const bool odd = (t & 1);
#pragma unroll
        for (int j = 0; j < 8; j++) {
            float v00 = __shfl_sync(0xffffffffu, sp[j][0], src0);
            float v01 = __shfl_sync(0xffffffffu, sp[j][1], src0);
            float v10 = __shfl_sync(0xffffffffu, sp[j][2], src0);
            float v11 = __shfl_sync(0xffffffffu, sp[j][3], src0);
            float v20 = __shfl_sync(0xffffffffu, sp[j][0], src0 + 2);
            float v21 = __shfl_sync(0xffffffffu, sp[j][1], src0 + 2);
            float v30 = __shfl_sync(0xffffffffu, sp[j][2], src0 + 2);
            float v31 = __shfl_sync(0xffffffffu, sp[j][3], src0 + 2);
            uint32 a[4];
            a[0] = __float_as_uint(tf32f(odd ? v01 : v00));
            a[1] = __float_as_uint(tf32f(odd ? v11 : v10));
            a[2] = __float_as_uint(tf32f(odd ? v21 : v20));
            a[3] = __float_as_uint(tf32f(odd ? v31 : v30));
#pragma unroll
            for (int nd = 0; nd < 8; nd++) {
                uint32 bb[2];
                bb[0] = __float_as_uint(Vs[8 * j + t][8 * nd + g]);
                bb[1] = __float_as_uint(Vs[8 * j + t + 4][8 * nd + g]);
                mma_tf32(o[nd], a, bb);
            }
        }
        __syncthreads();
    }

    // ---- epilogue ----
    float ia = 1.f / l_a, ib = 1.f / l_b;
    float* oa = O + ((size_t)b * S_LEN + q0 + wq + g) * DM + h * DK;
    float* ob = O + ((size_t)b * S_LEN + q0 + wq + g + 8) * DM + h * DK;
#pragma unroll
    for (int nd = 0; nd < 8; nd++) {
        float2 va = make_float2(o[nd][0] * ia, o[nd][1] * ia);
        *(float2*)(oa + 8 * nd + 2 * t) = va;
        float2 vb = make_float2(o[nd][2] * ib, o[nd][3] * ib);
        *(float2*)(ob + 8 * nd + 2 * t) = vb;
    }
}

// ---------------------------------------------------------------------------
// launch
// ---------------------------------------------------------------------------
extern "C" void kernel_launch(void* const* d_in, const int* in_sizes, int n_in,
                              void* d_out, int out_size)
{
    const float* q    = (const float*)d_in[0];
    const float* k    = (const float*)d_in[1];
    const float* v    = (const float*)d_in[2];
    const int*   mask = (const int*)  d_in[3];
    const float* W_q  = (const float*)d_in[4];
    const float* b_q  = (const float*)d_in[5];
    const float* W_k  = (const float*)d_in[6];
    const float* b_k  = (const float*)d_in[7];
    const float* W_v  = (const float*)d_in[8];
    const float* b_v  = (const float*)d_in[9];
    const float* W_o  = (const float*)d_in[10];
    const float* b_o  = (const float*)d_in[11];
    float* out = (float*)d_out;

    float *Qb, *Kb, *Vb, *Ab;
    cudaGetSymbolAddress((void**)&Qb, g_Q);
    cudaGetSymbolAddress((void**)&Kb, g_K);
    cudaGetSymbolAddress((void**)&Vb, g_V);
    cudaGetSymbolAddress((void**)&Ab, g_A);

    const int M = NB * S_LEN;           // 8192
    dim3 ggrid(DM / GBN, M / GBM);      // (8, 64)

    gemm_tf32<<<ggrid, 256>>>(q, W_q, b_q, Qb, M, DM, DM);
    gemm_tf32<<<ggrid, 256>>>(k, W_k, b_k, Kb, M, DM, DM);
    gemm_tf32<<<ggrid, 256>>>(v, W_v, b_v, Vb, M, DM, DM);

    dim3 agrid(S_LEN / FBQ, NH, NB);    // (32, 16, 4)
    flash_mma<<<agrid, 128>>>(Qb, Kb, Vb, mask, Ab);

    gemm_tf32<<<ggrid, 256>>>(Ab, W_o, b_o, out, M, DM, DM);
}